// round 17
// baseline (speedup 1.0000x reference)
#include <cuda_runtime.h>
#include <cuda_bf16.h>
#include <math_constants.h>

// CropSplitGT: out[h, w, n] = data[h, w, n] if (w,h) inside roi box n else 0.
// data (H, W, N) row-major, rois (4, N) = [x1; y1; x2; y2].
//
// Champion structure with H_PER=16: per-tile prologue (rois loads, divide,
// x-fold, mask build) amortized over 16 rows instead of 8. Two sequential
// MLP-8 batches (the proven-necessary load depth); 16-bit row-interval
// masks packed into two registers.

#define HH 512
#define WW 512
#define NN 400
#define N4 (NN / 4)            // 100 float4 per pixel
#define ROW4 (WW * N4)         // 51200 float4 per row
#define ROWB 819200            // row stride in BYTES
#define H_PER 16
#define GY (HH / H_PER)        // 32 bands
#define TPB 512
#define GX (ROW4 / TPB)        // 100 x-blocks

// Predicated 128-bit streaming load at [base + literal byte offset].
// Contents UNDEFINED when pred==0; caller's blend masks them.
#define LDG_CS_PRED_OFF(dst, pred, base, I)                              \
    asm("{\n\t"                                                          \
        ".reg .pred %%pp;\n\t"                                           \
        "setp.ne.u32 %%pp, %4, 0;\n\t"                                   \
        "@%%pp ld.global.cs.v4.f32 {%0, %1, %2, %3}, [%5 + %6];\n\t"     \
        "}"                                                              \
        : "=f"((dst).x), "=f"((dst).y), "=f"((dst).z), "=f"((dst).w)     \
        : "r"(pred), "l"(base), "n"((I) * (long)ROWB))

// 16-bit mask of rows i in [0,16) with (h0+i) in [y1, y2] (inclusive).
// y1 == +inf (x-miss fold) yields 0. Clamps keep shifts in [0,16].
__device__ __forceinline__ unsigned row_mask16(float y1, float y2, float h0f)
{
    int ilo = __float2int_ru(y1 - h0f);   // saturates on +inf
    int ihi = __float2int_rd(y2 - h0f);
    ilo = max(ilo, 0);   ilo = min(ilo, 16);
    ihi = min(ihi, 15);  ihi = max(ihi, -1);
    return ((1u << (ihi + 1)) - 1u) & ~((1u << ilo) - 1u);
}

__global__ __launch_bounds__(TPB) void crop_split_gt_kernel(
    const float4* __restrict__ data,
    const float*  __restrict__ rois,
    float4*       __restrict__ out)
{
    const unsigned tid = blockIdx.x * TPB + threadIdx.x;   // [0, ROW4)
    const unsigned w   = tid / N4;
    const unsigned n4  = tid - w * N4;
    const float wf = (float)w;

    const float4 x1 = __ldg((const float4*)(rois)          + n4);
    const float4 x2 = __ldg((const float4*)(rois + 2 * NN) + n4);
    float4 y1 = __ldg((const float4*)(rois + NN)     + n4);
    float4 y2 = __ldg((const float4*)(rois + 3 * NN) + n4);

    // Fold x-mask into y-range: outside [x1,x2] -> empty interval.
    if (!(wf >= x1.x && wf <= x2.x)) y1.x = CUDART_INF_F;
    if (!(wf >= x1.y && wf <= x2.y)) y1.y = CUDART_INF_F;
    if (!(wf >= x1.z && wf <= x2.z)) y1.z = CUDART_INF_F;
    if (!(wf >= x1.w && wf <= x2.w)) y1.w = CUDART_INF_F;

    const unsigned h0 = blockIdx.y * H_PER;
    const float h0f = (float)h0;

    // 16-bit row masks per component -> two packed registers:
    //   mlo: rows 0-7  (byte c = component c), mhi: rows 8-15.
    const unsigned r0 = row_mask16(y1.x, y2.x, h0f);
    const unsigned r1 = row_mask16(y1.y, y2.y, h0f);
    const unsigned r2 = row_mask16(y1.z, y2.z, h0f);
    const unsigned r3 = row_mask16(y1.w, y2.w, h0f);
    const unsigned mlo = (r0 & 0xFFu) | ((r1 & 0xFFu) << 8)
                       | ((r2 & 0xFFu) << 16) | ((r3 & 0xFFu) << 24);
    const unsigned mhi = (r0 >> 8) | ((r1 >> 8) << 8)
                       | ((r2 >> 8) << 16) | ((r3 >> 8) << 24);
    const unsigned anyw = r0 | r1 | r2 | r3;   // bit i: row i needs a read

    const unsigned base = h0 * (unsigned)ROW4 + tid;
    const float4* __restrict__ pbase = data + base;
    float4* __restrict__ obase = out + base;

    // ---- Batch A: rows 0-7, MLP 8 ----
    {
        float4 v[8];
        LDG_CS_PRED_OFF(v[0], anyw & 0x0001u, pbase, 0);
        LDG_CS_PRED_OFF(v[1], anyw & 0x0002u, pbase, 1);
        LDG_CS_PRED_OFF(v[2], anyw & 0x0004u, pbase, 2);
        LDG_CS_PRED_OFF(v[3], anyw & 0x0008u, pbase, 3);
        LDG_CS_PRED_OFF(v[4], anyw & 0x0010u, pbase, 4);
        LDG_CS_PRED_OFF(v[5], anyw & 0x0020u, pbase, 5);
        LDG_CS_PRED_OFF(v[6], anyw & 0x0040u, pbase, 6);
        LDG_CS_PRED_OFF(v[7], anyw & 0x0080u, pbase, 7);

        #pragma unroll
        for (int i = 0; i < 8; ++i) {
            const unsigned t = mlo >> i;
            float4 r;
            r.x = (t & 0x00000001u) ? v[i].x : 0.0f;
            r.y = (t & 0x00000100u) ? v[i].y : 0.0f;
            r.z = (t & 0x00010000u) ? v[i].z : 0.0f;
            r.w = (t & 0x01000000u) ? v[i].w : 0.0f;
            __stcs(obase + (unsigned)(i * ROW4), r);
        }
    }

    // ---- Batch B: rows 8-15, MLP 8 ----
    {
        float4 v[8];
        LDG_CS_PRED_OFF(v[0], anyw & 0x0100u, pbase, 8);
        LDG_CS_PRED_OFF(v[1], anyw & 0x0200u, pbase, 9);
        LDG_CS_PRED_OFF(v[2], anyw & 0x0400u, pbase, 10);
        LDG_CS_PRED_OFF(v[3], anyw & 0x0800u, pbase, 11);
        LDG_CS_PRED_OFF(v[4], anyw & 0x1000u, pbase, 12);
        LDG_CS_PRED_OFF(v[5], anyw & 0x2000u, pbase, 13);
        LDG_CS_PRED_OFF(v[6], anyw & 0x4000u, pbase, 14);
        LDG_CS_PRED_OFF(v[7], anyw & 0x8000u, pbase, 15);

        #pragma unroll
        for (int i = 0; i < 8; ++i) {
            const unsigned t = mhi >> i;
            float4 r;
            r.x = (t & 0x00000001u) ? v[i].x : 0.0f;
            r.y = (t & 0x00000100u) ? v[i].y : 0.0f;
            r.z = (t & 0x00010000u) ? v[i].z : 0.0f;
            r.w = (t & 0x01000000u) ? v[i].w : 0.0f;
            __stcs(obase + (unsigned)((i + 8) * ROW4), r);
        }
    }
}

extern "C" void kernel_launch(void* const* d_in, const int* in_sizes, int n_in,
                              void* d_out, int out_size)
{
    const float4* data = (const float4*)d_in[0];
    const float*  rois = (const float*)d_in[1];
    float4* out = (float4*)d_out;

    dim3 block(TPB);
    dim3 grid(GX, GY);   // 100 x 32 blocks, x-major
    crop_split_gt_kernel<<<grid, block>>>(data, rois, out);
}